// round 13
// baseline (speedup 1.0000x reference)
#include <cuda_runtime.h>
#include <cuda_bf16.h>

typedef unsigned long long ull;

#define Bn   512
#define Tn   256
#define Hn   256
#define HORn 22
#define BT   4
#define NC   64           // chunks: chunk C covers k = 4C..4C+3
#define NZS  18           // zr chunks in smem (9 per kh); [18,64) from L2 (23 per kh)
#define NTHR 1024
#define NCTA (Bn/BT)      // 128

// SMEM (floats/words):
//   uzr_sm : uint4[18*256] =  73728 B
//   uh_sm  : uint2[64*256] = 131072 B
//   hp     : float[4*256]  =   4096 B
//   rhp    : float[4*256]  =   4096 B   (epilogue scratch starts here: 16KB)
//   eps    : float[256*4]  =   4096 B
//   part   : float[8*256]  =   8192 B
//   sigq   : float[16]     =     64 B
#define SMEM_BYTES (73728 + 131072 + 4096 + 4096 + 4096 + 8192 + 64)  // 225344

__device__ uint4 g_uzr4[NC * 256];
__device__ uint2 g_uh2 [NC * 256];

static __device__ __forceinline__ unsigned bfp(float a, float b) {
    unsigned lo = (unsigned)__bfloat16_as_ushort(__float2bfloat16(a));
    unsigned hi = (unsigned)__bfloat16_as_ushort(__float2bfloat16(b));
    return lo | (hi << 16);
}

__global__ void ggru_pack_kernel(const float* __restrict__ Uz,
                                 const float* __restrict__ Ur,
                                 const float* __restrict__ Uh) {
    int idx = blockIdx.x * blockDim.x + threadIdx.x;
    if (idx >= NC * 256) return;
    int C = idx >> 8;
    int j = idx & 255;
    int k0 = 4 * C;
    uint4 w;
    w.x = bfp(Uz[(k0    ) * Hn + j], Uz[(k0 + 1) * Hn + j]);
    w.y = bfp(Ur[(k0    ) * Hn + j], Ur[(k0 + 1) * Hn + j]);
    w.z = bfp(Uz[(k0 + 2) * Hn + j], Uz[(k0 + 3) * Hn + j]);
    w.w = bfp(Ur[(k0 + 2) * Hn + j], Ur[(k0 + 3) * Hn + j]);
    g_uzr4[idx] = w;
    uint2 h;
    h.x = bfp(Uh[(k0    ) * Hn + j], Uh[(k0 + 1) * Hn + j]);
    h.y = bfp(Uh[(k0 + 2) * Hn + j], Uh[(k0 + 3) * Hn + j]);
    g_uh2[idx] = h;
}

// ---- f32x2 helpers ----
static __device__ __forceinline__ ull bfpair(unsigned w) {
    unsigned lo = w << 16;
    unsigned hi = w & 0xFFFF0000u;
    ull p;
    asm("mov.b64 %0, {%1, %2};" : "=l"(p) : "r"(lo), "r"(hi));
    return p;
}
static __device__ __forceinline__ ull fma2(ull a, ull b, ull c) {
    ull d;
    asm("fma.rn.f32x2 %0, %1, %2, %3;" : "=l"(d) : "l"(a), "l"(b), "l"(c));
    return d;
}
static __device__ __forceinline__ float red2(ull a) {
    unsigned lo, hi;
    asm("mov.b64 {%0, %1}, %2;" : "=r"(lo), "=r"(hi) : "l"(a));
    return __uint_as_float(lo) + __uint_as_float(hi);
}
static __device__ __forceinline__ float tanh_ap(float x) {
    float y;
    asm("tanh.approx.f32 %0, %1;" : "=f"(y) : "f"(x));
    return y;
}
static __device__ __forceinline__ float sig_ap(float x) {
    return fmaf(0.5f, tanh_ap(0.5f * x), 0.5f);
}
static __device__ __forceinline__ void gbar(int id) {
    asm volatile("bar.sync %0, 512;" :: "r"(id) : "memory");
}

__global__ void __launch_bounds__(NTHR, 1)
ggru_main_kernel(const float* __restrict__ x,
                 const float* __restrict__ Wzw, const float* __restrict__ Wzb,
                 const float* __restrict__ Uzb,
                 const float* __restrict__ Wrw, const float* __restrict__ Wrb,
                 const float* __restrict__ Urb,
                 const float* __restrict__ Whw, const float* __restrict__ Whb,
                 const float* __restrict__ Uhb,
                 const float* __restrict__ Wgw, const float* __restrict__ Wgb,
                 const float* __restrict__ p_om, const float* __restrict__ p_al,
                 const float* __restrict__ p_be, const float* __restrict__ p_ga,
                 const float* __restrict__ fc1w, const float* __restrict__ fc1b,
                 const float* __restrict__ fc2w, const float* __restrict__ fc2b,
                 float* __restrict__ out) {
    extern __shared__ unsigned char smem[];
    uint4* uzr_sm = (uint4*)smem;                       // zr chunks [0,18)
    uint2* uh_sm  = (uint2*)(uzr_sm + NZS * 256);       // all 64 uh chunks
    float* hp      = (float*)(uh_sm + NC * 256);        // [r][256]
    float* rhp     = hp + 1024;                         // also epilogue scratch base
    float* eps_sm  = rhp + 1024;                        // [t*4 + r]
    float* part    = eps_sm + 1024;                     // [8][256]
    float* sigq_sm = part + 2048;                       // [4]

    const int tid = threadIdx.x;
    const int j   = tid & 255;
    const int rh  = (tid >> 8) & 1;    // row-half: owns rows {2rh, 2rh+1}
    const int kh  = tid >> 9;          // k-half
    const int r0  = blockIdx.x * BT;
    const int rA  = 2 * rh;
    const int rB  = 2 * rh + 1;
    const int bid = 1 + rh;            // named barrier per rh stream

    // ---- prologue ----
    for (int i = tid; i < NZS * 256; i += NTHR) uzr_sm[i] = g_uzr4[i];
    for (int i = tid; i < NC * 256; i += NTHR)  uh_sm[i]  = g_uh2[i];
    for (int i = tid; i < Tn * BT; i += NTHR) {
        int t = i >> 2, r = i & 3;
        eps_sm[i] = x[(r0 + r) * Tn + t];
    }
    for (int i = tid; i < 1024; i += NTHR) hp[i] = 0.0f;

    // folded per-column gate constants (8 regs)
    const float wzw = Wzw[j], wrw = Wrw[j], whw = Whw[j];
    const float bz  = Wzb[j] + Uzb[j];
    const float br  = Wrb[j] + Urb[j];
    const float bh  = Whb[j] + Uhb[j];
    float gam = p_ga[0];
    const float gw  = gam * Wgw[j];
    const float gb  = gam * Wgb[j];

    float om_raw = p_om[0];
    float omega  = ((om_raw > 20.0f) ? om_raw : log1pf(expf(om_raw))) + 1e-6f;
    float aP     = 1.0f / (1.0f + expf(-p_al[0]));
    float bP     = (1.0f / (1.0f + expf(-p_be[0]))) * (1.0f - aP * 0.99f);

    float h_reg[2] = {0.f, 0.f};
    float epsq[2]  = {1e-6f, 1e-6f};
    float sigq[2]  = {1e-6f, 1e-6f};

    __syncthreads();

    // chunk assignment: kh=0 -> smem [0,9) + L2 [18,41); kh=1 -> smem [9,18) + L2 [41,64)
    const uint4* zr_s = uzr_sm + kh * 9 * 256 + j;
    const uint4* zr_g = g_uzr4 + (NZS + kh * 23) * 256 + j;
    const int CsB = kh * 9;
    const int CgB = NZS + kh * 23;
    const uint2* wh_s = uh_sm + kh * 32 * 256 + j;      // uh chunks [32kh, 32kh+32)

    for (int t = 0; t < Tn; t++) {
        float evA = eps_sm[t * 4 + rA];
        float evB = eps_sm[t * 4 + rB];
        float ginA = omega + aP * epsq[0] + bP * sigq[0];
        float ginB = omega + aP * epsq[1] + bP * sigq[1];
        epsq[0] = evA * evA; epsq[1] = evB * evB;
        sigq[0] = ginA;      sigq[1] = ginB;

        // ---- phase 1: z & r partial matvecs (own k-half, own 2 rows) ----
        ull az0 = 0, az1 = 0, ar0 = 0, ar1 = 0;
        {
            const ulonglong2* hqA = (const ulonglong2*)hp + rA * 64;
            const ulonglong2* hqB = (const ulonglong2*)hp + rB * 64;
#pragma unroll 4
            for (int c = 0; c < 23; c++) {
                uint4 w = __ldg(zr_g + c * 256);
                int C = CgB + c;
                ulonglong2 ha = hqA[C];
                ulonglong2 hb = hqB[C];
                ull za = bfpair(w.x), ra = bfpair(w.y);
                ull zc = bfpair(w.z), rc = bfpair(w.w);
                az0 = fma2(za, ha.x, az0); az0 = fma2(zc, ha.y, az0);
                az1 = fma2(za, hb.x, az1); az1 = fma2(zc, hb.y, az1);
                ar0 = fma2(ra, ha.x, ar0); ar0 = fma2(rc, ha.y, ar0);
                ar1 = fma2(ra, hb.x, ar1); ar1 = fma2(rc, hb.y, ar1);
            }
#pragma unroll 3
            for (int c = 0; c < 9; c++) {
                uint4 w = zr_s[c * 256];
                int C = CsB + c;
                ulonglong2 ha = hqA[C];
                ulonglong2 hb = hqB[C];
                ull za = bfpair(w.x), ra = bfpair(w.y);
                ull zc = bfpair(w.z), rc = bfpair(w.w);
                az0 = fma2(za, ha.x, az0); az0 = fma2(zc, ha.y, az0);
                az1 = fma2(za, hb.x, az1); az1 = fma2(zc, hb.y, az1);
                ar0 = fma2(ra, ha.x, ar0); ar0 = fma2(rc, ha.y, ar0);
                ar1 = fma2(ra, hb.x, ar1); ar1 = fma2(rc, hb.y, ar1);
            }
        }
        if (kh == 1) {
            part[(rh * 4 + 0) * 256 + j] = red2(az0);
            part[(rh * 4 + 1) * 256 + j] = red2(az1);
            part[(rh * 4 + 2) * 256 + j] = red2(ar0);
            part[(rh * 4 + 3) * 256 + j] = red2(ar1);
        }
        gbar(bid);

        float zA, zB;
        if (kh == 0) {
            float szA = red2(az0) + part[(rh * 4 + 0) * 256 + j];
            float szB = red2(az1) + part[(rh * 4 + 1) * 256 + j];
            float srA = red2(ar0) + part[(rh * 4 + 2) * 256 + j];
            float srB = red2(ar1) + part[(rh * 4 + 3) * 256 + j];
            zA = sig_ap(szA + fmaf(evA, wzw, bz));
            zB = sig_ap(szB + fmaf(evB, wzw, bz));
            float rgA = sig_ap(srA + fmaf(evA, wrw, br));
            float rgB = sig_ap(srB + fmaf(evB, wrw, br));
            rhp[rA * 256 + j] = rgA * h_reg[0];
            rhp[rB * 256 + j] = rgB * h_reg[1];
        }
        gbar(bid);

        // ---- phase 2: h_tilde partial matvec (own k-half of uh, all smem) ----
        ull ah0 = 0, ah1 = 0;
        {
            const ulonglong2* rqA = (const ulonglong2*)rhp + rA * 64 + kh * 32;
            const ulonglong2* rqB = (const ulonglong2*)rhp + rB * 64 + kh * 32;
#pragma unroll 8
            for (int c = 0; c < 32; c++) {
                uint2 w = wh_s[c * 256];
                ull ha_ = bfpair(w.x), hc_ = bfpair(w.y);
                ulonglong2 qa = rqA[c];
                ulonglong2 qb = rqB[c];
                ah0 = fma2(ha_, qa.x, ah0); ah0 = fma2(hc_, qa.y, ah0);
                ah1 = fma2(ha_, qb.x, ah1); ah1 = fma2(hc_, qb.y, ah1);
            }
        }
        if (kh == 1) {
            part[(rh * 2 + 0) * 256 + j] = red2(ah0);
            part[(rh * 2 + 1) * 256 + j] = red2(ah1);
        }
        gbar(bid);

        if (kh == 0) {
            float shA = red2(ah0) + part[(rh * 2 + 0) * 256 + j];
            float shB = red2(ah1) + part[(rh * 2 + 1) * 256 + j];
            float htA = tanh_ap(shA + fmaf(evA, whw, bh));
            float htB = tanh_ap(shB + fmaf(evB, whw, bh));
            float hhA = (1.0f - zA) * htA + zA * h_reg[0];
            float hhB = (1.0f - zB) * htB + zB * h_reg[1];
            float hnA = tanh_ap(hhA + fmaf(ginA, gw, gb));
            float hnB = tanh_ap(hhB + fmaf(ginB, gw, gb));
            h_reg[0] = hnA; h_reg[1] = hnB;
            hp[rA * 256 + j] = hnA;
            hp[rB * 256 + j] = hnB;
        }
        gbar(bid);
    }

    // stash sigma_sq (identical across all threads of a row's group)
    if (kh == 0 && j == 0) {
        sigq_sm[rA] = sigq[0];
        sigq_sm[rB] = sigq[1];
    }
    __syncthreads();

    // ---- epilogue: fc1 -> relu -> fc2 -> softplus -> vol ----
    // scratch = rhp (16KB spanning rhp+eps+part); hid at scratch+3072 floats
    float* scratch = rhp;
    float* hid = scratch + 3072;
    const int q = 2 * kh + rh;          // k-quarter [64q, 64q+64)
    {
        float acc[BT] = {0.f, 0.f, 0.f, 0.f};
        const int kb = q * 64;
        for (int k = kb; k < kb + 64; k++) {
            float f = fc1w[k * Hn + j];
#pragma unroll
            for (int r = 0; r < BT; r++) acc[r] = fmaf(hp[r * 256 + k], f, acc[r]);
        }
        if (q != 0) {
#pragma unroll
            for (int r = 0; r < BT; r++) scratch[((q - 1) * 4 + r) * 256 + j] = acc[r];
        }
        __syncthreads();
        if (q == 0) {
            float b1 = fc1b[j];
#pragma unroll
            for (int r = 0; r < BT; r++) {
                float s = acc[r] + b1;
                s += scratch[(0 * 4 + r) * 256 + j];
                s += scratch[(1 * 4 + r) * 256 + j];
                s += scratch[(2 * 4 + r) * 256 + j];
                hid[r * 256 + j] = fmaxf(s, 0.0f);
            }
        }
        __syncthreads();
    }

    if (q == 0 && j < BT * HORn) {        // 88 threads
        int r = j / HORn;
        int o = j - r * HORn;
        float s = 0.0f;
        for (int k = 0; k < Hn; k++) s = fmaf(hid[r * 256 + k], fc2w[k * HORn + o], s);
        s += fc2b[o];
        float nn = (s > 20.0f) ? s : log1pf(expf(s));
        float vb = sqrtf(sigq_sm[r] + 1e-8f);
        float vol = vb * (1.0f + nn);
        vol = fminf(fmaxf(vol, 0.01f), 10.0f);
        out[(r0 + r) * HORn + o] = vol;
    }
    if (q == 0 && j >= BT * HORn && j < BT * HORn + BT) {
        int r = j - BT * HORn;
        out[Bn * HORn + r0 + r] = sigq_sm[r];
    }
}

extern "C" void kernel_launch(void* const* d_in, const int* in_sizes, int n_in,
                              void* d_out, int out_size) {
    const float* x    = (const float*)d_in[0];
    const float* Wzw  = (const float*)d_in[1];
    const float* Wzb  = (const float*)d_in[2];
    const float* Uzw  = (const float*)d_in[3];
    const float* Uzb  = (const float*)d_in[4];
    const float* Wrw  = (const float*)d_in[5];
    const float* Wrb  = (const float*)d_in[6];
    const float* Urw  = (const float*)d_in[7];
    const float* Urb  = (const float*)d_in[8];
    const float* Whw  = (const float*)d_in[9];
    const float* Whb  = (const float*)d_in[10];
    const float* Uhw  = (const float*)d_in[11];
    const float* Uhb  = (const float*)d_in[12];
    const float* Wgw  = (const float*)d_in[13];
    const float* Wgb  = (const float*)d_in[14];
    const float* om   = (const float*)d_in[15];
    const float* al   = (const float*)d_in[16];
    const float* be   = (const float*)d_in[17];
    const float* ga   = (const float*)d_in[18];
    const float* fc1w = (const float*)d_in[19];
    const float* fc1b = (const float*)d_in[20];
    const float* fc2w = (const float*)d_in[21];
    const float* fc2b = (const float*)d_in[22];
    float* out = (float*)d_out;

    ggru_pack_kernel<<<(NC * 256 + 255) / 256, 256>>>(Uzw, Urw, Uhw);

    cudaFuncSetAttribute(ggru_main_kernel,
                         cudaFuncAttributeMaxDynamicSharedMemorySize, SMEM_BYTES);
    ggru_main_kernel<<<NCTA, NTHR, SMEM_BYTES>>>(
        x, Wzw, Wzb, Uzb, Wrw, Wrb, Urb, Whw, Whb, Uhb,
        Wgw, Wgb, om, al, be, ga, fc1w, fc1b, fc2w, fc2b, out);
}